// round 13
// baseline (speedup 1.0000x reference)
#include <cuda_runtime.h>

#define THREADS 128
#define S_CTA   32
#define PAD     36

#define OFF_HT    0                  // 128 x PAD : hT (alias: ctx, then x)
#define OFF_ARCH  4608               //  64 x PAD : archT (live until stage E)
#define OFF_QKV   6912               // 192 x PAD : qkvT (alias: x)
#define OFF_COLS  13824              // int[5*32]
#define OFF_HW    13984              // int[32]
#define OFF_HWEMB 14016              // float[4*68] hw_embed, stride 68 (bank-spread)
#define SMEM_FLOATS 14288
#define SMEM_BYTES  (SMEM_FLOATS * 4)

typedef unsigned long long ull;

__device__ float g_W1T[75 * 128];    // [col][k]
__device__ float g_W2T[128 * 64];    // [k][o]
__device__ float g_inT[64 * 192];    // [d][o]
__device__ float g_WoT[64 * 64];     // [d][o]
__device__ float g_W3T[64 * 32];     // [d][j]
__device__ float g_qkv0[4 * 192];
__device__ float g_s00[16];

__device__ __forceinline__ void FFMA2(ull& d, ull a, ull b) {
    asm("fma.rn.f32x2 %0, %1, %2, %0;" : "+l"(d) : "l"(a), "l"(b));
}
__device__ __forceinline__ void ADD2(ull& d, ull a) {
    asm("add.rn.f32x2 %0, %1, %0;" : "+l"(d) : "l"(a));
}
__device__ __forceinline__ ull PACK2(float x, float y) {
    ull v; asm("mov.b64 %0, {%1, %2};" : "=l"(v) : "f"(x), "f"(y)); return v;
}
__device__ __forceinline__ float2 UNPACK2(ull v) {
    float2 f; asm("mov.b64 {%0, %1}, %2;" : "=f"(f.x), "=f"(f.y) : "l"(v)); return f;
}

// ---- fused prep: transposes + hw token-0 tables ----
__global__ void prep_all(const float* __restrict__ W1,  const float* __restrict__ W2,
                         const float* __restrict__ ipw, const float* __restrict__ opw,
                         const float* __restrict__ W3,  const float* __restrict__ ipb,
                         const float* __restrict__ hw_embed)
{
    if (blockIdx.x < 40) {
        int t  = blockIdx.x * blockDim.x + threadIdx.x;
        int NT = 40 * blockDim.x;
        for (int i = t; i < 75 * 128; i += NT) g_W1T[i] = W1[(i & 127) * 75 + (i >> 7)];
        for (int i = t; i < 128 * 64; i += NT) g_W2T[i] = W2[(i & 63) * 128 + (i >> 6)];
        for (int i = t; i < 64 * 192; i += NT) g_inT[i] = ipw[(i % 192) * 64 + (i / 192)];
        for (int i = t; i < 64 * 64;  i += NT) g_WoT[i] = opw[(i & 63) * 64 + (i >> 6)];
        for (int i = t; i < 64 * 32;  i += NT) g_W3T[i] = W3[(i & 31) * 64 + (i >> 5)];
    } else {
        int t = threadIdx.x;
        for (int i = t; i < 768; i += blockDim.x) {
            int hw = i / 192, o = i % 192;
            float acc = ipb[o];
            #pragma unroll 8
            for (int d = 0; d < 64; d++) acc += ipw[o * 64 + d] * hw_embed[hw * 64 + d];
            g_qkv0[i] = acc;
        }
        __syncthreads();
        if (t < 16) {
            int hw = t >> 2, hh = t & 3;
            const float* q0 = g_qkv0 + hw * 192 + hh * 16;
            const float* k0 = q0 + 64;
            float acc = 0.f;
            #pragma unroll
            for (int j = 0; j < 16; j++) acc += q0[j] * k0[j];
            g_s00[t] = acc * 0.25f;
        }
    }
}

__global__ void __launch_bounds__(THREADS, 4)
mhlp_main(const int* __restrict__ hw_idx, const int* __restrict__ op_idx,
          const int* __restrict__ wd_idx, const float* __restrict__ hw_embed,
          const float* __restrict__ b1,   const float* __restrict__ b2,
          const float* __restrict__ ln1g, const float* __restrict__ ln1b,
          const float* __restrict__ ipb,  const float* __restrict__ opb,
          const float* __restrict__ ln2g, const float* __restrict__ ln2b,
          const float* __restrict__ b3,   const float* __restrict__ W4,
          const float* __restrict__ b4,   float* __restrict__ out)
{
    extern __shared__ float sm[];
    float* s_hT   = sm + OFF_HT;
    float* s_arch = sm + OFF_ARCH;
    float* s_qkv  = sm + OFF_QKV;
    int*   s_col  = (int*)(sm + OFF_COLS);
    int*   s_hw   = (int*)(sm + OFF_HW);
    float* s_hwe  = sm + OFF_HWEMB;  // [hw*68 + o], stride 68 kills hw-bank aliasing
    float* s_ctx  = sm + OFF_HT;     // alias: hT dead after stage B
    float* s_x    = sm + OFF_QKV;    // alias: qkv dead after stage D

    const int t    = threadIdx.x;
    const int base = blockIdx.x * S_CTA;
    const int lane = t & 31, warp = t >> 5;

    // stage 0: indices + hw embedding table into smem
    {
        int hwq = t >> 5;            // 128 threads cover 4x32 of the 4x64 table twice
        s_hwe[hwq * 68 + lane]      = hw_embed[hwq * 64 + lane];
        s_hwe[hwq * 68 + 32 + lane] = hw_embed[hwq * 64 + 32 + lane];
    }
    if (t < S_CTA) {
        s_hw[t] = hw_idx[base + t];
        #pragma unroll
        for (int l = 0; l < 5; l++) {
            int op = op_idx[(base + t) * 5 + l];
            int wd = wd_idx[(base + t) * 5 + l];
            s_col[l * S_CTA + t] = l * 15 + op * 3 + wd;
        }
    }
    __syncthreads();

    // stage A: h = relu(b1 + sum_l W1col) -> s_hT[k][s]
    {
        float bias[4];
        #pragma unroll
        for (int j = 0; j < 4; j++) bias[j] = __ldg(b1 + lane + 32 * j);
        #pragma unroll
        for (int grp = 0; grp < 2; grp++) {
            const int sbase = warp * 8 + grp * 4;
            float acc[4][4];   // [j][sample]
            #pragma unroll
            for (int i = 0; i < 4; i++)
                #pragma unroll
                for (int j = 0; j < 4; j++) acc[j][i] = bias[j];
            #pragma unroll
            for (int l = 0; l < 5; l++) {
                #pragma unroll
                for (int i = 0; i < 4; i++) {
                    int c = s_col[l * S_CTA + sbase + i];
                    const float* row = g_W1T + c * 128 + lane;
                    #pragma unroll
                    for (int j = 0; j < 4; j++)
                        acc[j][i] += __ldg(row + 32 * j);
                }
            }
            #pragma unroll
            for (int j = 0; j < 4; j++) {
                float4 v = make_float4(fmaxf(acc[j][0], 0.f), fmaxf(acc[j][1], 0.f),
                                       fmaxf(acc[j][2], 0.f), fmaxf(acc[j][3], 0.f));
                *(float4*)(s_hT + (lane + 32 * j) * PAD + sbase) = v;
            }
        }
    }
    __syncthreads();

    const int sg = t & 7, og = t >> 3;
    const int s0 = sg * 4, o0 = og * 4;

    // stage B: arch_pre = h @ W2^T + b2 -> s_arch[o][s]
    {
        ull acc[2][4] = {};
        #pragma unroll 4
        for (int k = 0; k < 128; k++) {
            ulonglong2 h = *(const ulonglong2*)(s_hT + k * PAD + s0);
            float4 w = __ldg((const float4*)(g_W2T + k * 64 + o0));
            ull w0 = PACK2(w.x, w.x), w1 = PACK2(w.y, w.y);
            ull w2 = PACK2(w.z, w.z), w3 = PACK2(w.w, w.w);
            FFMA2(acc[0][0], h.x, w0); FFMA2(acc[0][1], h.x, w1);
            FFMA2(acc[0][2], h.x, w2); FFMA2(acc[0][3], h.x, w3);
            FFMA2(acc[1][0], h.y, w0); FFMA2(acc[1][1], h.y, w1);
            FFMA2(acc[1][2], h.y, w2); FFMA2(acc[1][3], h.y, w3);
        }
        #pragma unroll
        for (int j = 0; j < 4; j++) {
            float bb = __ldg(b2 + o0 + j);
            ull bb2 = PACK2(bb, bb);
            ADD2(acc[0][j], bb2); ADD2(acc[1][j], bb2);
            *(ull*)(s_arch + (o0 + j) * PAD + s0)     = acc[0][j];
            *(ull*)(s_arch + (o0 + j) * PAD + s0 + 2) = acc[1][j];
        }
    }
    __syncthreads();

    // stage B2: LayerNorm1 — 4 threads/sample, shfl reduce
    {
        const int s = t >> 2, g = t & 3;
        float v[16], sum = 0.f, sq = 0.f;
        #pragma unroll
        for (int j = 0; j < 16; j++) {
            v[j] = s_arch[(4 * j + g) * PAD + s];
            sum += v[j]; sq += v[j] * v[j];
        }
        sum += __shfl_xor_sync(0xffffffffu, sum, 1); sq += __shfl_xor_sync(0xffffffffu, sq, 1);
        sum += __shfl_xor_sync(0xffffffffu, sum, 2); sq += __shfl_xor_sync(0xffffffffu, sq, 2);
        float m   = sum * (1.f / 64.f);
        float var = fmaxf(sq * (1.f / 64.f) - m * m, 0.f);
        float inv = rsqrtf(var + 1e-5f);
        #pragma unroll
        for (int j = 0; j < 16; j++) {
            int d = 4 * j + g;
            s_arch[d * PAD + s] = (v[j] - m) * inv * __ldg(ln1g + d) + __ldg(ln1b + d);
        }
    }
    __syncthreads();

    // stage C: qkv1 = arch @ in_proj^T + b -> s_qkv[o][s]  (fused over 3 ob)
    {
        ull acc[3][2][4] = {};
        #pragma unroll 2
        for (int d = 0; d < 64; d++) {
            ulonglong2 h = *(const ulonglong2*)(s_arch + d * PAD + s0);
            #pragma unroll
            for (int ob = 0; ob < 3; ob++) {
                float4 w = __ldg((const float4*)(g_inT + d * 192 + ob * 64 + o0));
                ull w0 = PACK2(w.x, w.x), w1 = PACK2(w.y, w.y);
                ull w2 = PACK2(w.z, w.z), w3 = PACK2(w.w, w.w);
                FFMA2(acc[ob][0][0], h.x, w0); FFMA2(acc[ob][0][1], h.x, w1);
                FFMA2(acc[ob][0][2], h.x, w2); FFMA2(acc[ob][0][3], h.x, w3);
                FFMA2(acc[ob][1][0], h.y, w0); FFMA2(acc[ob][1][1], h.y, w1);
                FFMA2(acc[ob][1][2], h.y, w2); FFMA2(acc[ob][1][3], h.y, w3);
            }
        }
        #pragma unroll
        for (int ob = 0; ob < 3; ob++) {
            #pragma unroll
            for (int j = 0; j < 4; j++) {
                int oo = ob * 64 + o0 + j;
                float bb = __ldg(ipb + oo);
                ull bb2 = PACK2(bb, bb);
                ADD2(acc[ob][0][j], bb2); ADD2(acc[ob][1][j], bb2);
                *(ull*)(s_qkv + oo * PAD + s0)     = acc[ob][0][j];
                *(ull*)(s_qkv + oo * PAD + s0 + 2) = acc[ob][1][j];
            }
        }
    }
    __syncthreads();

    // stage D: attention (1 thread per (sample, head)) -> s_ctx[tok*64+d][s]
    // q0/k0/v0 via float4 vector loads: same lines touched once, not 4x.
    {
        const int s = t & 31, hh = t >> 5;
        const int rq = hh * 16;
        float q1[16], k1[16], v1[16];
        #pragma unroll
        for (int j = 0; j < 16; j++) {
            q1[j] = s_qkv[(rq + j) * PAD + s];
            k1[j] = s_qkv[(64 + rq + j) * PAD + s];
            v1[j] = s_qkv[(128 + rq + j) * PAD + s];
        }
        const int hw = s_hw[s];
        const float* gq = g_qkv0 + hw * 192 + rq;
        float q0a[16], k0a[16], v0a[16];
        #pragma unroll
        for (int p = 0; p < 4; p++) {
            *(float4*)(q0a + 4 * p) = __ldg((const float4*)(gq + 4 * p));
            *(float4*)(k0a + 4 * p) = __ldg((const float4*)(gq + 64 + 4 * p));
            *(float4*)(v0a + 4 * p) = __ldg((const float4*)(gq + 128 + 4 * p));
        }
        float s01 = 0.f, s10 = 0.f, s11 = 0.f;
        #pragma unroll
        for (int j = 0; j < 16; j++) {
            s01 += q0a[j] * k1[j];
            s10 += q1[j] * k0a[j];
            s11 += q1[j] * k1[j];
        }
        s01 *= 0.25f; s10 *= 0.25f; s11 *= 0.25f;
        float s00 = __ldg(g_s00 + hw * 4 + hh);
        float m0 = fmaxf(s00, s01);
        float e00 = __expf(s00 - m0), e01 = __expf(s01 - m0);
        float r0 = __frcp_rn(e00 + e01);
        float a00 = e00 * r0, a01 = e01 * r0;
        float m1 = fmaxf(s10, s11);
        float e10 = __expf(s10 - m1), e11 = __expf(s11 - m1);
        float r1 = __frcp_rn(e10 + e11);
        float a10 = e10 * r1, a11 = e11 * r1;
        #pragma unroll
        for (int j = 0; j < 16; j++) {
            s_ctx[(rq + j) * PAD + s]      = a00 * v0a[j] + a01 * v1[j];
            s_ctx[(64 + rq + j) * PAD + s] = a10 * v0a[j] + a11 * v1[j];
        }
    }
    __syncthreads();

    // stage E: attn_out + residual; read ctx fully into regs, barrier, write x over it
    {
        ull acc[2][2][4] = {};
        #pragma unroll 2
        for (int d = 0; d < 64; d++) {
            float4 w = __ldg((const float4*)(g_WoT + d * 64 + o0));
            ull w0 = PACK2(w.x, w.x), w1 = PACK2(w.y, w.y);
            ull w2 = PACK2(w.z, w.z), w3 = PACK2(w.w, w.w);
            ulonglong2 c0 = *(const ulonglong2*)(s_ctx + d * PAD + s0);
            ulonglong2 c1 = *(const ulonglong2*)(s_ctx + (64 + d) * PAD + s0);
            FFMA2(acc[0][0][0], c0.x, w0); FFMA2(acc[0][0][1], c0.x, w1);
            FFMA2(acc[0][0][2], c0.x, w2); FFMA2(acc[0][0][3], c0.x, w3);
            FFMA2(acc[0][1][0], c0.y, w0); FFMA2(acc[0][1][1], c0.y, w1);
            FFMA2(acc[0][1][2], c0.y, w2); FFMA2(acc[0][1][3], c0.y, w3);
            FFMA2(acc[1][0][0], c1.x, w0); FFMA2(acc[1][0][1], c1.x, w1);
            FFMA2(acc[1][0][2], c1.x, w2); FFMA2(acc[1][0][3], c1.x, w3);
            FFMA2(acc[1][1][0], c1.y, w0); FFMA2(acc[1][1][1], c1.y, w1);
            FFMA2(acc[1][1][2], c1.y, w2); FFMA2(acc[1][1][3], c1.y, w3);
        }
        __syncthreads();   // all ctx reads done before x overwrites the region
        #pragma unroll
        for (int tok = 0; tok < 2; tok++) {
            #pragma unroll
            for (int j = 0; j < 4; j++) {
                float bb = __ldg(opb + o0 + j);
                #pragma unroll
                for (int i = 0; i < 4; i++) {
                    float2 f = UNPACK2(acc[tok][i >> 1][j]);
                    float a  = (i & 1) ? f.y : f.x;
                    float res = tok ? s_arch[(o0 + j) * PAD + s0 + i]
                                    : s_hwe[s_hw[s0 + i] * 68 + o0 + j];
                    s_x[(tok * 64 + o0 + j) * PAD + s0 + i] = a + bb + res;
                }
            }
        }
    }
    __syncthreads();

    // stage E2: LayerNorm2 — 2 threads/(tok,sample), shfl reduce
    {
        const int row = t >> 1, g = t & 1;
        const int s = row & 31, tok = row >> 5;
        float* xp = s_x + tok * 64 * PAD + s;
        float sum = 0.f, sq = 0.f;
        #pragma unroll 8
        for (int j = 0; j < 32; j++) {
            float v = xp[(2 * j + g) * PAD];
            sum += v; sq += v * v;
        }
        sum += __shfl_xor_sync(0xffffffffu, sum, 1);
        sq  += __shfl_xor_sync(0xffffffffu, sq, 1);
        float m   = sum * (1.f / 64.f);
        float var = fmaxf(sq * (1.f / 64.f) - m * m, 0.f);
        float inv = rsqrtf(var + 1e-5f);
        #pragma unroll 8
        for (int j = 0; j < 32; j++) {
            int d = 2 * j + g;
            float v = (xp[d * PAD] - m) * inv;
            xp[d * PAD] = v * __ldg(ln2g + d) + __ldg(ln2b + d);
        }
    }
    __syncthreads();

    // stage F: pooled -> relu(@W3^T+b3) @ W4^T + b4 -> out
    {
        const int s = t >> 2, hh = t & 3;
        ulonglong2 b3a = *(const ulonglong2*)(b3 + hh * 8);
        ulonglong2 b3b = *(const ulonglong2*)(b3 + hh * 8 + 4);
        ull acc[4] = { b3a.x, b3a.y, b3b.x, b3b.y };
        #pragma unroll 4
        for (int d = 0; d < 64; d++) {
            float p = 0.5f * (s_x[d * PAD + s] + s_x[(64 + d) * PAD + s]);
            ull pd = PACK2(p, p);
            ulonglong2 w0 = *(const ulonglong2*)(g_W3T + d * 32 + hh * 8);
            ulonglong2 w1 = *(const ulonglong2*)(g_W3T + d * 32 + hh * 8 + 4);
            FFMA2(acc[0], pd, w0.x); FFMA2(acc[1], pd, w0.y);
            FFMA2(acc[2], pd, w1.x); FFMA2(acc[3], pd, w1.y);
        }
        float part = 0.f;
        #pragma unroll
        for (int o = 0; o < 4; o++) {
            float2 f = UNPACK2(acc[o]);
            part += fmaxf(f.x, 0.f) * __ldg(W4 + hh * 8 + 2 * o);
            part += fmaxf(f.y, 0.f) * __ldg(W4 + hh * 8 + 2 * o + 1);
        }
        part += __shfl_down_sync(0xffffffffu, part, 2);
        part += __shfl_down_sync(0xffffffffu, part, 1);
        if (hh == 0) out[base + s] = part + __ldg(b4);
    }
}

extern "C" void kernel_launch(void* const* d_in, const int* in_sizes, int n_in,
                              void* d_out, int out_size)
{
    const int*   hw_idx   = (const int*)  d_in[0];
    const int*   op_idx   = (const int*)  d_in[1];
    const int*   wd_idx   = (const int*)  d_in[2];
    const float* hw_embed = (const float*)d_in[3];
    const float* W1       = (const float*)d_in[4];
    const float* b1       = (const float*)d_in[5];
    const float* W2       = (const float*)d_in[6];
    const float* b2       = (const float*)d_in[7];
    const float* ln1g     = (const float*)d_in[8];
    const float* ln1b     = (const float*)d_in[9];
    const float* ipw      = (const float*)d_in[10];
    const float* ipb      = (const float*)d_in[11];
    const float* opw      = (const float*)d_in[12];
    const float* opb      = (const float*)d_in[13];
    const float* ln2g     = (const float*)d_in[14];
    const float* ln2b     = (const float*)d_in[15];
    const float* W3       = (const float*)d_in[16];
    const float* b3       = (const float*)d_in[17];
    const float* W4       = (const float*)d_in[18];
    const float* b4       = (const float*)d_in[19];
    float* out = (float*)d_out;

    static bool init_done = false;
    if (!init_done) {
        cudaFuncSetAttribute(mhlp_main, cudaFuncAttributeMaxDynamicSharedMemorySize, SMEM_BYTES);
        init_done = true;
    }

    prep_all<<<41, 256>>>(W1, W2, ipw, opw, W3, ipb, hw_embed);

    const int B = in_sizes[0];
    mhlp_main<<<B / S_CTA, THREADS, SMEM_BYTES>>>(
        hw_idx, op_idx, wd_idx, hw_embed, b1, b2, ln1g, ln1b,
        ipb, opb, ln2g, ln2b, b3, W4, b4, out);
}

// round 14
// speedup vs baseline: 1.0468x; 1.0468x over previous
#include <cuda_runtime.h>

#define THREADS 128
#define S_CTA   32
#define PAD     36

// Aliased arena (saves the 27KB qkv buffer -> 5 CTAs/SM):
//   R1   (128 rows x 36): hT -> q(rows 0-63)+k(rows 64-127) -> ctx -> x
//   ARCH ( 64 rows x 36): arch embedding (live stage B..E)
//   TAIL ( 64 rows x 36): v
#define OFF_R1    0
#define OFF_ARCH  4608
#define OFF_TAIL  6912
#define OFF_COLS  9216               // int[5*32]
#define OFF_HW    9376               // int[32]
#define OFF_HWEMB 9408               // float[4*68] hw_embed, stride 68
#define SMEM_FLOATS 9680
#define SMEM_BYTES  (SMEM_FLOATS * 4)

typedef unsigned long long ull;

__device__ float g_W1T[75 * 128];    // [col][k]
__device__ float g_W2T[128 * 64];    // [k][o]
__device__ float g_inT[64 * 192];    // [d][o]
__device__ float g_WoT[64 * 64];     // [d][o]
__device__ float g_W3T[64 * 32];     // [d][j]
__device__ float g_qkv0[4 * 192];
__device__ float g_s00[16];

__device__ __forceinline__ void FFMA2(ull& d, ull a, ull b) {
    asm("fma.rn.f32x2 %0, %1, %2, %0;" : "+l"(d) : "l"(a), "l"(b));
}
__device__ __forceinline__ void ADD2(ull& d, ull a) {
    asm("add.rn.f32x2 %0, %1, %0;" : "+l"(d) : "l"(a));
}
__device__ __forceinline__ ull PACK2(float x, float y) {
    ull v; asm("mov.b64 %0, {%1, %2};" : "=l"(v) : "f"(x), "f"(y)); return v;
}
__device__ __forceinline__ float2 UNPACK2(ull v) {
    float2 f; asm("mov.b64 {%0, %1}, %2;" : "=f"(f.x), "=f"(f.y) : "l"(v)); return f;
}

// ---- fused prep: transposes + hw token-0 tables ----
__global__ void prep_all(const float* __restrict__ W1,  const float* __restrict__ W2,
                         const float* __restrict__ ipw, const float* __restrict__ opw,
                         const float* __restrict__ W3,  const float* __restrict__ ipb,
                         const float* __restrict__ hw_embed)
{
    if (blockIdx.x < 40) {
        int t  = blockIdx.x * blockDim.x + threadIdx.x;
        int NT = 40 * blockDim.x;
        for (int i = t; i < 75 * 128; i += NT) g_W1T[i] = W1[(i & 127) * 75 + (i >> 7)];
        for (int i = t; i < 128 * 64; i += NT) g_W2T[i] = W2[(i & 63) * 128 + (i >> 6)];
        for (int i = t; i < 64 * 192; i += NT) g_inT[i] = ipw[(i % 192) * 64 + (i / 192)];
        for (int i = t; i < 64 * 64;  i += NT) g_WoT[i] = opw[(i & 63) * 64 + (i >> 6)];
        for (int i = t; i < 64 * 32;  i += NT) g_W3T[i] = W3[(i & 31) * 64 + (i >> 5)];
    } else {
        int t = threadIdx.x;
        for (int i = t; i < 768; i += blockDim.x) {
            int hw = i / 192, o = i % 192;
            float acc = ipb[o];
            #pragma unroll 8
            for (int d = 0; d < 64; d++) acc += ipw[o * 64 + d] * hw_embed[hw * 64 + d];
            g_qkv0[i] = acc;
        }
        __syncthreads();
        if (t < 16) {
            int hw = t >> 2, hh = t & 3;
            const float* q0 = g_qkv0 + hw * 192 + hh * 16;
            const float* k0 = q0 + 64;
            float acc = 0.f;
            #pragma unroll
            for (int j = 0; j < 16; j++) acc += q0[j] * k0[j];
            g_s00[t] = acc * 0.25f;
        }
    }
}

__global__ void __launch_bounds__(THREADS, 5)
mhlp_main(const int* __restrict__ hw_idx, const int* __restrict__ op_idx,
          const int* __restrict__ wd_idx, const float* __restrict__ hw_embed,
          const float* __restrict__ b1,   const float* __restrict__ b2,
          const float* __restrict__ ln1g, const float* __restrict__ ln1b,
          const float* __restrict__ ipb,  const float* __restrict__ opb,
          const float* __restrict__ ln2g, const float* __restrict__ ln2b,
          const float* __restrict__ b3,   const float* __restrict__ W4,
          const float* __restrict__ b4,   float* __restrict__ out)
{
    extern __shared__ float sm[];
    float* s_r1   = sm + OFF_R1;     // hT -> q,k -> ctx -> x
    float* s_arch = sm + OFF_ARCH;
    float* s_tail = sm + OFF_TAIL;   // v
    int*   s_col  = (int*)(sm + OFF_COLS);
    int*   s_hw   = (int*)(sm + OFF_HW);
    float* s_hwe  = sm + OFF_HWEMB;

    const int t    = threadIdx.x;
    const int base = blockIdx.x * S_CTA;
    const int lane = t & 31, warp = t >> 5;

    // stage 0: indices + hw embedding table into smem
    {
        int hwq = t >> 5;
        s_hwe[hwq * 68 + lane]      = hw_embed[hwq * 64 + lane];
        s_hwe[hwq * 68 + 32 + lane] = hw_embed[hwq * 64 + 32 + lane];
    }
    if (t < S_CTA) {
        s_hw[t] = hw_idx[base + t];
        #pragma unroll
        for (int l = 0; l < 5; l++) {
            int op = op_idx[(base + t) * 5 + l];
            int wd = wd_idx[(base + t) * 5 + l];
            s_col[l * S_CTA + t] = l * 15 + op * 3 + wd;
        }
    }
    __syncthreads();

    // stage A: h = relu(b1 + sum_l W1col) -> R1[k][s]
    {
        float bias[4];
        #pragma unroll
        for (int j = 0; j < 4; j++) bias[j] = __ldg(b1 + lane + 32 * j);
        #pragma unroll
        for (int grp = 0; grp < 2; grp++) {
            const int sbase = warp * 8 + grp * 4;
            float acc[4][4];   // [j][sample]
            #pragma unroll
            for (int i = 0; i < 4; i++)
                #pragma unroll
                for (int j = 0; j < 4; j++) acc[j][i] = bias[j];
            #pragma unroll
            for (int l = 0; l < 5; l++) {
                #pragma unroll
                for (int i = 0; i < 4; i++) {
                    int c = s_col[l * S_CTA + sbase + i];
                    const float* row = g_W1T + c * 128 + lane;
                    #pragma unroll
                    for (int j = 0; j < 4; j++)
                        acc[j][i] += __ldg(row + 32 * j);
                }
            }
            #pragma unroll
            for (int j = 0; j < 4; j++) {
                float4 v = make_float4(fmaxf(acc[j][0], 0.f), fmaxf(acc[j][1], 0.f),
                                       fmaxf(acc[j][2], 0.f), fmaxf(acc[j][3], 0.f));
                *(float4*)(s_r1 + (lane + 32 * j) * PAD + sbase) = v;
            }
        }
    }
    __syncthreads();

    const int sg = t & 7, og = t >> 3;
    const int s0 = sg * 4, o0 = og * 4;

    // stage B: arch_pre = h @ W2^T + b2 -> arch[o][s]
    {
        ull acc[2][4] = {};
        #pragma unroll 4
        for (int k = 0; k < 128; k++) {
            ulonglong2 h = *(const ulonglong2*)(s_r1 + k * PAD + s0);
            float4 w = __ldg((const float4*)(g_W2T + k * 64 + o0));
            ull w0 = PACK2(w.x, w.x), w1 = PACK2(w.y, w.y);
            ull w2 = PACK2(w.z, w.z), w3 = PACK2(w.w, w.w);
            FFMA2(acc[0][0], h.x, w0); FFMA2(acc[0][1], h.x, w1);
            FFMA2(acc[0][2], h.x, w2); FFMA2(acc[0][3], h.x, w3);
            FFMA2(acc[1][0], h.y, w0); FFMA2(acc[1][1], h.y, w1);
            FFMA2(acc[1][2], h.y, w2); FFMA2(acc[1][3], h.y, w3);
        }
        #pragma unroll
        for (int j = 0; j < 4; j++) {
            float bb = __ldg(b2 + o0 + j);
            ull bb2 = PACK2(bb, bb);
            ADD2(acc[0][j], bb2); ADD2(acc[1][j], bb2);
            *(ull*)(s_arch + (o0 + j) * PAD + s0)     = acc[0][j];
            *(ull*)(s_arch + (o0 + j) * PAD + s0 + 2) = acc[1][j];
        }
    }
    __syncthreads();

    // stage B2: LayerNorm1 — 4 threads/sample, shfl reduce
    {
        const int s = t >> 2, g = t & 3;
        float v[16], sum = 0.f, sq = 0.f;
        #pragma unroll
        for (int j = 0; j < 16; j++) {
            v[j] = s_arch[(4 * j + g) * PAD + s];
            sum += v[j]; sq += v[j] * v[j];
        }
        sum += __shfl_xor_sync(0xffffffffu, sum, 1); sq += __shfl_xor_sync(0xffffffffu, sq, 1);
        sum += __shfl_xor_sync(0xffffffffu, sum, 2); sq += __shfl_xor_sync(0xffffffffu, sq, 2);
        float m   = sum * (1.f / 64.f);
        float var = fmaxf(sq * (1.f / 64.f) - m * m, 0.f);
        float inv = rsqrtf(var + 1e-5f);
        #pragma unroll
        for (int j = 0; j < 16; j++) {
            int d = 4 * j + g;
            s_arch[d * PAD + s] = (v[j] - m) * inv * __ldg(ln1g + d) + __ldg(ln1b + d);
        }
    }
    __syncthreads();

    // stage C: qkv1 = arch @ in_proj^T + b.
    // q -> R1 rows 0-63, k -> R1 rows 64-127, v -> TAIL rows 0-63.
    // Epilogue is three straight-line affine blocks (NO conditional pointers —
    // that ternary is what broke FFMA2 packing in the R9 build).
    {
        ull acc[3][2][4] = {};
        #pragma unroll 2
        for (int d = 0; d < 64; d++) {
            ulonglong2 h = *(const ulonglong2*)(s_arch + d * PAD + s0);
            #pragma unroll
            for (int ob = 0; ob < 3; ob++) {
                float4 w = __ldg((const float4*)(g_inT + d * 192 + ob * 64 + o0));
                ull w0 = PACK2(w.x, w.x), w1 = PACK2(w.y, w.y);
                ull w2 = PACK2(w.z, w.z), w3 = PACK2(w.w, w.w);
                FFMA2(acc[ob][0][0], h.x, w0); FFMA2(acc[ob][0][1], h.x, w1);
                FFMA2(acc[ob][0][2], h.x, w2); FFMA2(acc[ob][0][3], h.x, w3);
                FFMA2(acc[ob][1][0], h.y, w0); FFMA2(acc[ob][1][1], h.y, w1);
                FFMA2(acc[ob][1][2], h.y, w2); FFMA2(acc[ob][1][3], h.y, w3);
            }
        }
        #pragma unroll
        for (int j = 0; j < 4; j++) {          // q
            float bb = __ldg(ipb + o0 + j);
            ull bb2 = PACK2(bb, bb);
            ADD2(acc[0][0][j], bb2); ADD2(acc[0][1][j], bb2);
            *(ull*)(s_r1 + (o0 + j) * PAD + s0)     = acc[0][0][j];
            *(ull*)(s_r1 + (o0 + j) * PAD + s0 + 2) = acc[0][1][j];
        }
        #pragma unroll
        for (int j = 0; j < 4; j++) {          // k
            float bb = __ldg(ipb + 64 + o0 + j);
            ull bb2 = PACK2(bb, bb);
            ADD2(acc[1][0][j], bb2); ADD2(acc[1][1][j], bb2);
            *(ull*)(s_r1 + (64 + o0 + j) * PAD + s0)     = acc[1][0][j];
            *(ull*)(s_r1 + (64 + o0 + j) * PAD + s0 + 2) = acc[1][1][j];
        }
        #pragma unroll
        for (int j = 0; j < 4; j++) {          // v
            float bb = __ldg(ipb + 128 + o0 + j);
            ull bb2 = PACK2(bb, bb);
            ADD2(acc[2][0][j], bb2); ADD2(acc[2][1][j], bb2);
            *(ull*)(s_tail + (o0 + j) * PAD + s0)     = acc[2][0][j];
            *(ull*)(s_tail + (o0 + j) * PAD + s0 + 2) = acc[2][1][j];
        }
    }
    __syncthreads();

    // stage D: attention. Reads q/k from R1, v from TAIL; writes ctx back over
    // its OWN head's q/k rows (per-(row,col) read-then-write by the same thread,
    // disjoint across threads -> no barrier needed before stores).
    {
        const int s = t & 31, hh = t >> 5;
        const int rq = hh * 16;
        float q1[16], k1[16], v1[16];
        #pragma unroll
        for (int j = 0; j < 16; j++) {
            q1[j] = s_r1[(rq + j) * PAD + s];
            k1[j] = s_r1[(64 + rq + j) * PAD + s];
            v1[j] = s_tail[(rq + j) * PAD + s];
        }
        const int hw = s_hw[s];
        const float* gq = g_qkv0 + hw * 192 + rq;
        float q0a[16], k0a[16], v0a[16];
        #pragma unroll
        for (int p = 0; p < 4; p++) {
            *(float4*)(q0a + 4 * p) = __ldg((const float4*)(gq + 4 * p));
            *(float4*)(k0a + 4 * p) = __ldg((const float4*)(gq + 64 + 4 * p));
            *(float4*)(v0a + 4 * p) = __ldg((const float4*)(gq + 128 + 4 * p));
        }
        float s01 = 0.f, s10 = 0.f, s11 = 0.f;
        #pragma unroll
        for (int j = 0; j < 16; j++) {
            s01 += q0a[j] * k1[j];
            s10 += q1[j] * k0a[j];
            s11 += q1[j] * k1[j];
        }
        s01 *= 0.25f; s10 *= 0.25f; s11 *= 0.25f;
        float s00 = __ldg(g_s00 + hw * 4 + hh);
        float m0 = fmaxf(s00, s01);
        float e00 = __expf(s00 - m0), e01 = __expf(s01 - m0);
        float r0 = __frcp_rn(e00 + e01);
        float a00 = e00 * r0, a01 = e01 * r0;
        float m1 = fmaxf(s10, s11);
        float e10 = __expf(s10 - m1), e11 = __expf(s11 - m1);
        float r1 = __frcp_rn(e10 + e11);
        float a10 = e10 * r1, a11 = e11 * r1;
        #pragma unroll
        for (int j = 0; j < 16; j++) {
            s_r1[(rq + j) * PAD + s]      = a00 * v0a[j] + a01 * v1[j];  // ctx tok0
            s_r1[(64 + rq + j) * PAD + s] = a10 * v0a[j] + a11 * v1[j];  // ctx tok1
        }
    }
    __syncthreads();

    // stage E: attn_out + residual; read ctx fully into regs, barrier, write x over R1
    {
        ull acc[2][2][4] = {};
        #pragma unroll 2
        for (int d = 0; d < 64; d++) {
            float4 w = __ldg((const float4*)(g_WoT + d * 64 + o0));
            ull w0 = PACK2(w.x, w.x), w1 = PACK2(w.y, w.y);
            ull w2 = PACK2(w.z, w.z), w3 = PACK2(w.w, w.w);
            ulonglong2 c0 = *(const ulonglong2*)(s_r1 + d * PAD + s0);
            ulonglong2 c1 = *(const ulonglong2*)(s_r1 + (64 + d) * PAD + s0);
            FFMA2(acc[0][0][0], c0.x, w0); FFMA2(acc[0][0][1], c0.x, w1);
            FFMA2(acc[0][0][2], c0.x, w2); FFMA2(acc[0][0][3], c0.x, w3);
            FFMA2(acc[0][1][0], c0.y, w0); FFMA2(acc[0][1][1], c0.y, w1);
            FFMA2(acc[0][1][2], c0.y, w2); FFMA2(acc[0][1][3], c0.y, w3);
            FFMA2(acc[1][0][0], c1.x, w0); FFMA2(acc[1][0][1], c1.x, w1);
            FFMA2(acc[1][0][2], c1.x, w2); FFMA2(acc[1][0][3], c1.x, w3);
            FFMA2(acc[1][1][0], c1.y, w0); FFMA2(acc[1][1][1], c1.y, w1);
            FFMA2(acc[1][1][2], c1.y, w2); FFMA2(acc[1][1][3], c1.y, w3);
        }
        __syncthreads();   // all ctx reads done before x overwrites R1
        #pragma unroll
        for (int tok = 0; tok < 2; tok++) {
            #pragma unroll
            for (int j = 0; j < 4; j++) {
                float bb = __ldg(opb + o0 + j);
                #pragma unroll
                for (int i = 0; i < 4; i++) {
                    float2 f = UNPACK2(acc[tok][i >> 1][j]);
                    float a  = (i & 1) ? f.y : f.x;
                    float res = tok ? s_arch[(o0 + j) * PAD + s0 + i]
                                    : s_hwe[s_hw[s0 + i] * 68 + o0 + j];
                    s_r1[(tok * 64 + o0 + j) * PAD + s0 + i] = a + bb + res;
                }
            }
        }
    }
    __syncthreads();

    // stage E2: LayerNorm2 — 2 threads/(tok,sample), shfl reduce
    {
        const int row = t >> 1, g = t & 1;
        const int s = row & 31, tok = row >> 5;
        float* xp = s_r1 + tok * 64 * PAD + s;
        float sum = 0.f, sq = 0.f;
        #pragma unroll 8
        for (int j = 0; j < 32; j++) {
            float v = xp[(2 * j + g) * PAD];
            sum += v; sq += v * v;
        }
        sum += __shfl_xor_sync(0xffffffffu, sum, 1);
        sq  += __shfl_xor_sync(0xffffffffu, sq, 1);
        float m   = sum * (1.f / 64.f);
        float var = fmaxf(sq * (1.f / 64.f) - m * m, 0.f);
        float inv = rsqrtf(var + 1e-5f);
        #pragma unroll 8
        for (int j = 0; j < 32; j++) {
            int d = 2 * j + g;
            float v = (xp[d * PAD] - m) * inv;
            xp[d * PAD] = v * __ldg(ln2g + d) + __ldg(ln2b + d);
        }
    }
    __syncthreads();

    // stage F: pooled -> relu(@W3^T+b3) @ W4^T + b4 -> out
    {
        const int s = t >> 2, hh = t & 3;
        ulonglong2 b3a = *(const ulonglong2*)(b3 + hh * 8);
        ulonglong2 b3b = *(const ulonglong2*)(b3 + hh * 8 + 4);
        ull acc[4] = { b3a.x, b3a.y, b3b.x, b3b.y };
        #pragma unroll 4
        for (int d = 0; d < 64; d++) {
            float p = 0.5f * (s_r1[d * PAD + s] + s_r1[(64 + d) * PAD + s]);
            ull pd = PACK2(p, p);
            ulonglong2 w0 = *(const ulonglong2*)(g_W3T + d * 32 + hh * 8);
            ulonglong2 w1 = *(const ulonglong2*)(g_W3T + d * 32 + hh * 8 + 4);
            FFMA2(acc[0], pd, w0.x); FFMA2(acc[1], pd, w0.y);
            FFMA2(acc[2], pd, w1.x); FFMA2(acc[3], pd, w1.y);
        }
        float part = 0.f;
        #pragma unroll
        for (int o = 0; o < 4; o++) {
            float2 f = UNPACK2(acc[o]);
            part += fmaxf(f.x, 0.f) * __ldg(W4 + hh * 8 + 2 * o);
            part += fmaxf(f.y, 0.f) * __ldg(W4 + hh * 8 + 2 * o + 1);
        }
        part += __shfl_down_sync(0xffffffffu, part, 2);
        part += __shfl_down_sync(0xffffffffu, part, 1);
        if (hh == 0) out[base + s] = part + __ldg(b4);
    }
}

extern "C" void kernel_launch(void* const* d_in, const int* in_sizes, int n_in,
                              void* d_out, int out_size)
{
    const int*   hw_idx   = (const int*)  d_in[0];
    const int*   op_idx   = (const int*)  d_in[1];
    const int*   wd_idx   = (const int*)  d_in[2];
    const float* hw_embed = (const float*)d_in[3];
    const float* W1       = (const float*)d_in[4];
    const float* b1       = (const float*)d_in[5];
    const float* W2       = (const float*)d_in[6];
    const float* b2       = (const float*)d_in[7];
    const float* ln1g     = (const float*)d_in[8];
    const float* ln1b     = (const float*)d_in[9];
    const float* ipw      = (const float*)d_in[10];
    const float* ipb      = (const float*)d_in[11];
    const float* opw      = (const float*)d_in[12];
    const float* opb      = (const float*)d_in[13];
    const float* ln2g     = (const float*)d_in[14];
    const float* ln2b     = (const float*)d_in[15];
    const float* W3       = (const float*)d_in[16];
    const float* b3       = (const float*)d_in[17];
    const float* W4       = (const float*)d_in[18];
    const float* b4       = (const float*)d_in[19];
    float* out = (float*)d_out;

    static bool init_done = false;
    if (!init_done) {
        cudaFuncSetAttribute(mhlp_main, cudaFuncAttributeMaxDynamicSharedMemorySize, SMEM_BYTES);
        init_done = true;
    }

    prep_all<<<41, 256>>>(W1, W2, ipw, opw, W3, ipb, hw_embed);

    const int B = in_sizes[0];
    mhlp_main<<<B / S_CTA, THREADS, SMEM_BYTES>>>(
        hw_idx, op_idx, wd_idx, hw_embed, b1, b2, ln1g, ln1b,
        ipb, opb, ln2g, ln2b, b3, W4, b4, out);
}

// round 15
// speedup vs baseline: 1.1217x; 1.0716x over previous
#include <cuda_runtime.h>

#define THREADS 128
#define S_CTA   32
#define PAD     36

// Aliased arena (5 CTAs/SM):
//   R1   (128 rows x 36): hT -> q(0-63)+k(64-127) -> ctx -> x -> pooled(0-63)
//   ARCH ( 64 rows x 36): arch embedding (live stage B..E)
//   TAIL ( 64 rows x 36): v
#define OFF_R1    0
#define OFF_ARCH  4608
#define OFF_TAIL  6912
#define OFF_COLS  9216               // int[5*32]
#define OFF_HW    9376               // int[32]
#define OFF_HWEMB 9408               // float[4*68] hw_embed, stride 68
#define SMEM_FLOATS 9680
#define SMEM_BYTES  (SMEM_FLOATS * 4)

typedef unsigned long long ull;

__device__ float g_W1T[75 * 128];    // [col][k]
__device__ float g_W2T[128 * 64];    // [k][o]
__device__ float g_inT[64 * 192];    // [d][o]
__device__ float g_WoT[64 * 64];     // [d][o]
__device__ float g_W3T[64 * 32];     // [d][j]
__device__ float g_qkv0[4 * 192];
__device__ float g_s00[16];

__device__ __forceinline__ void FFMA2(ull& d, ull a, ull b) {
    asm("fma.rn.f32x2 %0, %1, %2, %0;" : "+l"(d) : "l"(a), "l"(b));
}
__device__ __forceinline__ void ADD2(ull& d, ull a) {
    asm("add.rn.f32x2 %0, %1, %0;" : "+l"(d) : "l"(a));
}
__device__ __forceinline__ ull PACK2(float x, float y) {
    ull v; asm("mov.b64 %0, {%1, %2};" : "=l"(v) : "f"(x), "f"(y)); return v;
}
__device__ __forceinline__ float2 UNPACK2(ull v) {
    float2 f; asm("mov.b64 {%0, %1}, %2;" : "=f"(f.x), "=f"(f.y) : "l"(v)); return f;
}

// ---- fused prep: transposes + hw token-0 tables ----
__global__ void prep_all(const float* __restrict__ W1,  const float* __restrict__ W2,
                         const float* __restrict__ ipw, const float* __restrict__ opw,
                         const float* __restrict__ W3,  const float* __restrict__ ipb,
                         const float* __restrict__ hw_embed)
{
    if (blockIdx.x < 40) {
        int t  = blockIdx.x * blockDim.x + threadIdx.x;
        int NT = 40 * blockDim.x;
        for (int i = t; i < 75 * 128; i += NT) g_W1T[i] = W1[(i & 127) * 75 + (i >> 7)];
        for (int i = t; i < 128 * 64; i += NT) g_W2T[i] = W2[(i & 63) * 128 + (i >> 6)];
        for (int i = t; i < 64 * 192; i += NT) g_inT[i] = ipw[(i % 192) * 64 + (i / 192)];
        for (int i = t; i < 64 * 64;  i += NT) g_WoT[i] = opw[(i & 63) * 64 + (i >> 6)];
        for (int i = t; i < 64 * 32;  i += NT) g_W3T[i] = W3[(i & 31) * 64 + (i >> 5)];
    } else {
        int t = threadIdx.x;
        for (int i = t; i < 768; i += blockDim.x) {
            int hw = i / 192, o = i % 192;
            float acc = ipb[o];
            #pragma unroll 8
            for (int d = 0; d < 64; d++) acc += ipw[o * 64 + d] * hw_embed[hw * 64 + d];
            g_qkv0[i] = acc;
        }
        __syncthreads();
        if (t < 16) {
            int hw = t >> 2, hh = t & 3;
            const float* q0 = g_qkv0 + hw * 192 + hh * 16;
            const float* k0 = q0 + 64;
            float acc = 0.f;
            #pragma unroll
            for (int j = 0; j < 16; j++) acc += q0[j] * k0[j];
            g_s00[t] = acc * 0.25f;
        }
    }
}

__global__ void __launch_bounds__(THREADS, 5)
mhlp_main(const int* __restrict__ hw_idx, const int* __restrict__ op_idx,
          const int* __restrict__ wd_idx, const float* __restrict__ hw_embed,
          const float* __restrict__ b1,   const float* __restrict__ b2,
          const float* __restrict__ ln1g, const float* __restrict__ ln1b,
          const float* __restrict__ ipb,  const float* __restrict__ opb,
          const float* __restrict__ ln2g, const float* __restrict__ ln2b,
          const float* __restrict__ b3,   const float* __restrict__ W4,
          const float* __restrict__ b4,   float* __restrict__ out)
{
    extern __shared__ float sm[];
    float* s_r1   = sm + OFF_R1;
    float* s_arch = sm + OFF_ARCH;
    float* s_tail = sm + OFF_TAIL;
    int*   s_col  = (int*)(sm + OFF_COLS);
    int*   s_hw   = (int*)(sm + OFF_HW);
    float* s_hwe  = sm + OFF_HWEMB;

    const int t    = threadIdx.x;
    const int base = blockIdx.x * S_CTA;
    const int lane = t & 31, warp = t >> 5;

    // stage 0: indices + hw embedding table into smem
    {
        int hwq = t >> 5;
        s_hwe[hwq * 68 + lane]      = hw_embed[hwq * 64 + lane];
        s_hwe[hwq * 68 + 32 + lane] = hw_embed[hwq * 64 + 32 + lane];
    }
    if (t < S_CTA) {
        s_hw[t] = hw_idx[base + t];
        #pragma unroll
        for (int l = 0; l < 5; l++) {
            int op = op_idx[(base + t) * 5 + l];
            int wd = wd_idx[(base + t) * 5 + l];
            s_col[l * S_CTA + t] = l * 15 + op * 3 + wd;
        }
    }
    __syncthreads();

    // stage A: h = relu(b1 + sum_l W1col) -> R1[k][s]
    {
        float bias[4];
        #pragma unroll
        for (int j = 0; j < 4; j++) bias[j] = __ldg(b1 + lane + 32 * j);
        #pragma unroll
        for (int grp = 0; grp < 2; grp++) {
            const int sbase = warp * 8 + grp * 4;
            float acc[4][4];
            #pragma unroll
            for (int i = 0; i < 4; i++)
                #pragma unroll
                for (int j = 0; j < 4; j++) acc[j][i] = bias[j];
            #pragma unroll
            for (int l = 0; l < 5; l++) {
                #pragma unroll
                for (int i = 0; i < 4; i++) {
                    int c = s_col[l * S_CTA + sbase + i];
                    const float* row = g_W1T + c * 128 + lane;
                    #pragma unroll
                    for (int j = 0; j < 4; j++)
                        acc[j][i] += __ldg(row + 32 * j);
                }
            }
            #pragma unroll
            for (int j = 0; j < 4; j++) {
                float4 v = make_float4(fmaxf(acc[j][0], 0.f), fmaxf(acc[j][1], 0.f),
                                       fmaxf(acc[j][2], 0.f), fmaxf(acc[j][3], 0.f));
                *(float4*)(s_r1 + (lane + 32 * j) * PAD + sbase) = v;
            }
        }
    }
    __syncthreads();

    const int sg = t & 7, og = t >> 3;
    const int s0 = sg * 4, o0 = og * 4;

    // stage B: arch_pre = h @ W2^T + b2 -> arch[o][s]
    {
        ull acc[2][4] = {};
        #pragma unroll 4
        for (int k = 0; k < 128; k++) {
            ulonglong2 h = *(const ulonglong2*)(s_r1 + k * PAD + s0);
            float4 w = __ldg((const float4*)(g_W2T + k * 64 + o0));
            ull w0 = PACK2(w.x, w.x), w1 = PACK2(w.y, w.y);
            ull w2 = PACK2(w.z, w.z), w3 = PACK2(w.w, w.w);
            FFMA2(acc[0][0], h.x, w0); FFMA2(acc[0][1], h.x, w1);
            FFMA2(acc[0][2], h.x, w2); FFMA2(acc[0][3], h.x, w3);
            FFMA2(acc[1][0], h.y, w0); FFMA2(acc[1][1], h.y, w1);
            FFMA2(acc[1][2], h.y, w2); FFMA2(acc[1][3], h.y, w3);
        }
        #pragma unroll
        for (int j = 0; j < 4; j++) {
            float bb = __ldg(b2 + o0 + j);
            ull bb2 = PACK2(bb, bb);
            ADD2(acc[0][j], bb2); ADD2(acc[1][j], bb2);
            *(ull*)(s_arch + (o0 + j) * PAD + s0)     = acc[0][j];
            *(ull*)(s_arch + (o0 + j) * PAD + s0 + 2) = acc[1][j];
        }
    }
    __syncthreads();

    // stage B2: LayerNorm1 — 4 threads/sample, shfl reduce
    {
        const int s = t >> 2, g = t & 3;
        float v[16], sum = 0.f, sq = 0.f;
        #pragma unroll
        for (int j = 0; j < 16; j++) {
            v[j] = s_arch[(4 * j + g) * PAD + s];
            sum += v[j]; sq += v[j] * v[j];
        }
        sum += __shfl_xor_sync(0xffffffffu, sum, 1); sq += __shfl_xor_sync(0xffffffffu, sq, 1);
        sum += __shfl_xor_sync(0xffffffffu, sum, 2); sq += __shfl_xor_sync(0xffffffffu, sq, 2);
        float m   = sum * (1.f / 64.f);
        float var = fmaxf(sq * (1.f / 64.f) - m * m, 0.f);
        float inv = rsqrtf(var + 1e-5f);
        #pragma unroll
        for (int j = 0; j < 16; j++) {
            int d = 4 * j + g;
            s_arch[d * PAD + s] = (v[j] - m) * inv * __ldg(ln1g + d) + __ldg(ln1b + d);
        }
    }
    __syncthreads();

    // stage C: qkv1 = arch @ in_proj^T + b.  q->R1[0:64), k->R1[64:128), v->TAIL.
    // Straight-line affine epilogue (keeps FFMA2 packing intact).
    {
        ull acc[3][2][4] = {};
        #pragma unroll 2
        for (int d = 0; d < 64; d++) {
            ulonglong2 h = *(const ulonglong2*)(s_arch + d * PAD + s0);
            #pragma unroll
            for (int ob = 0; ob < 3; ob++) {
                float4 w = __ldg((const float4*)(g_inT + d * 192 + ob * 64 + o0));
                ull w0 = PACK2(w.x, w.x), w1 = PACK2(w.y, w.y);
                ull w2 = PACK2(w.z, w.z), w3 = PACK2(w.w, w.w);
                FFMA2(acc[ob][0][0], h.x, w0); FFMA2(acc[ob][0][1], h.x, w1);
                FFMA2(acc[ob][0][2], h.x, w2); FFMA2(acc[ob][0][3], h.x, w3);
                FFMA2(acc[ob][1][0], h.y, w0); FFMA2(acc[ob][1][1], h.y, w1);
                FFMA2(acc[ob][1][2], h.y, w2); FFMA2(acc[ob][1][3], h.y, w3);
            }
        }
        #pragma unroll
        for (int j = 0; j < 4; j++) {          // q
            float bb = __ldg(ipb + o0 + j);
            ull bb2 = PACK2(bb, bb);
            ADD2(acc[0][0][j], bb2); ADD2(acc[0][1][j], bb2);
            *(ull*)(s_r1 + (o0 + j) * PAD + s0)     = acc[0][0][j];
            *(ull*)(s_r1 + (o0 + j) * PAD + s0 + 2) = acc[0][1][j];
        }
        #pragma unroll
        for (int j = 0; j < 4; j++) {          // k
            float bb = __ldg(ipb + 64 + o0 + j);
            ull bb2 = PACK2(bb, bb);
            ADD2(acc[1][0][j], bb2); ADD2(acc[1][1][j], bb2);
            *(ull*)(s_r1 + (64 + o0 + j) * PAD + s0)     = acc[1][0][j];
            *(ull*)(s_r1 + (64 + o0 + j) * PAD + s0 + 2) = acc[1][1][j];
        }
        #pragma unroll
        for (int j = 0; j < 4; j++) {          // v
            float bb = __ldg(ipb + 128 + o0 + j);
            ull bb2 = PACK2(bb, bb);
            ADD2(acc[2][0][j], bb2); ADD2(acc[2][1][j], bb2);
            *(ull*)(s_tail + (o0 + j) * PAD + s0)     = acc[2][0][j];
            *(ull*)(s_tail + (o0 + j) * PAD + s0 + 2) = acc[2][1][j];
        }
    }
    __syncthreads();

    // stage D: attention; writes ctx over its own head's q/k rows (thread-disjoint)
    {
        const int s = t & 31, hh = t >> 5;
        const int rq = hh * 16;
        float q1[16], k1[16], v1[16];
        #pragma unroll
        for (int j = 0; j < 16; j++) {
            q1[j] = s_r1[(rq + j) * PAD + s];
            k1[j] = s_r1[(64 + rq + j) * PAD + s];
            v1[j] = s_tail[(rq + j) * PAD + s];
        }
        const int hw = s_hw[s];
        const float* gq = g_qkv0 + hw * 192 + rq;
        float q0a[16], k0a[16], v0a[16];
        #pragma unroll
        for (int p = 0; p < 4; p++) {
            *(float4*)(q0a + 4 * p) = __ldg((const float4*)(gq + 4 * p));
            *(float4*)(k0a + 4 * p) = __ldg((const float4*)(gq + 64 + 4 * p));
            *(float4*)(v0a + 4 * p) = __ldg((const float4*)(gq + 128 + 4 * p));
        }
        float s01 = 0.f, s10 = 0.f, s11 = 0.f;
        #pragma unroll
        for (int j = 0; j < 16; j++) {
            s01 += q0a[j] * k1[j];
            s10 += q1[j] * k0a[j];
            s11 += q1[j] * k1[j];
        }
        s01 *= 0.25f; s10 *= 0.25f; s11 *= 0.25f;
        float s00 = __ldg(g_s00 + hw * 4 + hh);
        float m0 = fmaxf(s00, s01);
        float e00 = __expf(s00 - m0), e01 = __expf(s01 - m0);
        float r0 = __frcp_rn(e00 + e01);
        float a00 = e00 * r0, a01 = e01 * r0;
        float m1 = fmaxf(s10, s11);
        float e10 = __expf(s10 - m1), e11 = __expf(s11 - m1);
        float r1 = __frcp_rn(e10 + e11);
        float a10 = e10 * r1, a11 = e11 * r1;
        #pragma unroll
        for (int j = 0; j < 16; j++) {
            s_r1[(rq + j) * PAD + s]      = a00 * v0a[j] + a01 * v1[j];
            s_r1[(64 + rq + j) * PAD + s] = a10 * v0a[j] + a11 * v1[j];
        }
    }
    __syncthreads();

    // stage E: attn_out + residual; packed epilogue (ull stores, packed residual adds)
    {
        ull acc[2][2][4] = {};
        #pragma unroll 2
        for (int d = 0; d < 64; d++) {
            float4 w = __ldg((const float4*)(g_WoT + d * 64 + o0));
            ull w0 = PACK2(w.x, w.x), w1 = PACK2(w.y, w.y);
            ull w2 = PACK2(w.z, w.z), w3 = PACK2(w.w, w.w);
            ulonglong2 c0 = *(const ulonglong2*)(s_r1 + d * PAD + s0);
            ulonglong2 c1 = *(const ulonglong2*)(s_r1 + (64 + d) * PAD + s0);
            FFMA2(acc[0][0][0], c0.x, w0); FFMA2(acc[0][0][1], c0.x, w1);
            FFMA2(acc[0][0][2], c0.x, w2); FFMA2(acc[0][0][3], c0.x, w3);
            FFMA2(acc[0][1][0], c0.y, w0); FFMA2(acc[0][1][1], c0.y, w1);
            FFMA2(acc[0][1][2], c0.y, w2); FFMA2(acc[0][1][3], c0.y, w3);
            FFMA2(acc[1][0][0], c1.x, w0); FFMA2(acc[1][0][1], c1.x, w1);
            FFMA2(acc[1][0][2], c1.x, w2); FFMA2(acc[1][0][3], c1.x, w3);
            FFMA2(acc[1][1][0], c1.y, w0); FFMA2(acc[1][1][1], c1.y, w1);
            FFMA2(acc[1][1][2], c1.y, w2); FFMA2(acc[1][1][3], c1.y, w3);
        }
        __syncthreads();   // all ctx reads done before x overwrites R1
        const int hw0 = s_hw[s0],     hw1 = s_hw[s0 + 1];
        const int hw2 = s_hw[s0 + 2], hw3 = s_hw[s0 + 3];
        #pragma unroll
        for (int j = 0; j < 4; j++) {
            float bb = __ldg(opb + o0 + j);
            ull bb2 = PACK2(bb, bb);
            // token 0: hw-embedding residual (packed sample pairs)
            ull r0 = PACK2(s_hwe[hw0 * 68 + o0 + j], s_hwe[hw1 * 68 + o0 + j]);
            ull r1 = PACK2(s_hwe[hw2 * 68 + o0 + j], s_hwe[hw3 * 68 + o0 + j]);
            ADD2(acc[0][0][j], bb2); ADD2(acc[0][0][j], r0);
            ADD2(acc[0][1][j], bb2); ADD2(acc[0][1][j], r1);
            *(ull*)(s_r1 + (o0 + j) * PAD + s0)     = acc[0][0][j];
            *(ull*)(s_r1 + (o0 + j) * PAD + s0 + 2) = acc[0][1][j];
            // token 1: arch residual (contiguous packed pairs in smem)
            ull ra = *(const ull*)(s_arch + (o0 + j) * PAD + s0);
            ull rb = *(const ull*)(s_arch + (o0 + j) * PAD + s0 + 2);
            ADD2(acc[1][0][j], bb2); ADD2(acc[1][0][j], ra);
            ADD2(acc[1][1][j], bb2); ADD2(acc[1][1][j], rb);
            *(ull*)(s_r1 + (64 + o0 + j) * PAD + s0)     = acc[1][0][j];
            *(ull*)(s_r1 + (64 + o0 + j) * PAD + s0 + 2) = acc[1][1][j];
        }
    }
    __syncthreads();

    // stage E2+pool (fused): 4 threads/sample handle BOTH tokens in regs,
    // write only the pooled value 0.5*(ln(x0)+ln(x1)) to rows 0-63.
    // Each thread writes only locations it itself read (tok0) -> no hazard.
    {
        const int s = t >> 2, g = t & 3;
        float v0[16], v1[16];
        float sum0 = 0.f, sq0 = 0.f, sum1 = 0.f, sq1 = 0.f;
        #pragma unroll
        for (int j = 0; j < 16; j++) {
            v0[j] = s_r1[(4 * j + g) * PAD + s];
            v1[j] = s_r1[(64 + 4 * j + g) * PAD + s];
            sum0 += v0[j]; sq0 += v0[j] * v0[j];
            sum1 += v1[j]; sq1 += v1[j] * v1[j];
        }
        sum0 += __shfl_xor_sync(0xffffffffu, sum0, 1); sq0 += __shfl_xor_sync(0xffffffffu, sq0, 1);
        sum0 += __shfl_xor_sync(0xffffffffu, sum0, 2); sq0 += __shfl_xor_sync(0xffffffffu, sq0, 2);
        sum1 += __shfl_xor_sync(0xffffffffu, sum1, 1); sq1 += __shfl_xor_sync(0xffffffffu, sq1, 1);
        sum1 += __shfl_xor_sync(0xffffffffu, sum1, 2); sq1 += __shfl_xor_sync(0xffffffffu, sq1, 2);
        float m0   = sum0 * (1.f / 64.f);
        float var0 = fmaxf(sq0 * (1.f / 64.f) - m0 * m0, 0.f);
        float inv0 = rsqrtf(var0 + 1e-5f);
        float m1   = sum1 * (1.f / 64.f);
        float var1 = fmaxf(sq1 * (1.f / 64.f) - m1 * m1, 0.f);
        float inv1 = rsqrtf(var1 + 1e-5f);
        #pragma unroll
        for (int j = 0; j < 16; j++) {
            int d = 4 * j + g;
            float gg = __ldg(ln2g + d), bbv = __ldg(ln2b + d);
            float n0 = (v0[j] - m0) * inv0 * gg + bbv;
            float n1 = (v1[j] - m1) * inv1 * gg + bbv;
            s_r1[d * PAD + s] = 0.5f * (n0 + n1);
        }
    }
    __syncthreads();

    // stage F: pooled (rows 0-63) -> relu(@W3^T+b3) @ W4^T + b4 -> out
    {
        const int s = t >> 2, hh = t & 3;
        ulonglong2 b3a = *(const ulonglong2*)(b3 + hh * 8);
        ulonglong2 b3b = *(const ulonglong2*)(b3 + hh * 8 + 4);
        ull acc[4] = { b3a.x, b3a.y, b3b.x, b3b.y };
        #pragma unroll 4
        for (int d = 0; d < 64; d++) {
            float p = s_r1[d * PAD + s];
            ull pd = PACK2(p, p);
            ulonglong2 w0 = *(const ulonglong2*)(g_W3T + d * 32 + hh * 8);
            ulonglong2 w1 = *(const ulonglong2*)(g_W3T + d * 32 + hh * 8 + 4);
            FFMA2(acc[0], pd, w0.x); FFMA2(acc[1], pd, w0.y);
            FFMA2(acc[2], pd, w1.x); FFMA2(acc[3], pd, w1.y);
        }
        float part = 0.f;
        #pragma unroll
        for (int o = 0; o < 4; o++) {
            float2 f = UNPACK2(acc[o]);
            part += fmaxf(f.x, 0.f) * __ldg(W4 + hh * 8 + 2 * o);
            part += fmaxf(f.y, 0.f) * __ldg(W4 + hh * 8 + 2 * o + 1);
        }
        part += __shfl_down_sync(0xffffffffu, part, 2);
        part += __shfl_down_sync(0xffffffffu, part, 1);
        if (hh == 0) out[base + s] = part + __ldg(b4);
    }
}

extern "C" void kernel_launch(void* const* d_in, const int* in_sizes, int n_in,
                              void* d_out, int out_size)
{
    const int*   hw_idx   = (const int*)  d_in[0];
    const int*   op_idx   = (const int*)  d_in[1];
    const int*   wd_idx   = (const int*)  d_in[2];
    const float* hw_embed = (const float*)d_in[3];
    const float* W1       = (const float*)d_in[4];
    const float* b1       = (const float*)d_in[5];
    const float* W2       = (const float*)d_in[6];
    const float* b2       = (const float*)d_in[7];
    const float* ln1g     = (const float*)d_in[8];
    const float* ln1b     = (const float*)d_in[9];
    const float* ipw      = (const float*)d_in[10];
    const float* ipb      = (const float*)d_in[11];
    const float* opw      = (const float*)d_in[12];
    const float* opb      = (const float*)d_in[13];
    const float* ln2g     = (const float*)d_in[14];
    const float* ln2b     = (const float*)d_in[15];
    const float* W3       = (const float*)d_in[16];
    const float* b3       = (const float*)d_in[17];
    const float* W4       = (const float*)d_in[18];
    const float* b4       = (const float*)d_in[19];
    float* out = (float*)d_out;

    static bool init_done = false;
    if (!init_done) {
        cudaFuncSetAttribute(mhlp_main, cudaFuncAttributeMaxDynamicSharedMemorySize, SMEM_BYTES);
        init_done = true;
    }

    prep_all<<<41, 256>>>(W1, W2, ipw, opw, W3, ipb, hw_embed);

    const int B = in_sizes[0];
    mhlp_main<<<B / S_CTA, THREADS, SMEM_BYTES>>>(
        hw_idx, op_idx, wd_idx, hw_embed, b1, b2, ln1g, ln1b,
        ipb, opb, ln2g, ln2b, b3, W4, b4, out);
}